// round 11
// baseline (speedup 1.0000x reference)
#include <cuda_runtime.h>
#include <cuda_bf16.h>
#include <cstdint>

// ---------------------------------------------------------------------------
// FastAttention (Performer / FAVOR+) — TF32 warp-MMA, DOUBLE stab-cancelled
//   b=4, h=8 (BH=32), n=4096, d=64, m=266, e=64
// k-side: kp = Ck(E_k + eps·e^s), Ck cancels →
//   k1: E_k = exp(dn k@P^T − diag) bf16; s = max(d)
//   k2: ctx = ΣE_k v, km = ΣE_k, vsum = Σv
// q-side: qp = Cq(E_q + eps·e^{mx_r}), Cq cancels per row →
//   k3: phase1 mma + EXP IN EPILOGUE → tf32 qp = E_q; row max → atomicMax
//       phase2b: dsum = ΣE_q·KM (+kms);  dinv = 1/(dsum + εr·kms)
//       phase3: out = (E_q@CTX + εr·S)·dinv,  S[e] = Σ_m CTX[m][e]
//   where KM = km + L·eps', CTX = ctx + eps'·vsum, eps' = eps·e^s,
//         εr = eps·e^{mx_r}
// Bank rules: g-rows stride 68; tg-rows stride 72 (words).
// SMEM CLIFF: k3 <= 115,712 B for 2 CTAs/SM (this build: 115,200 B).
// ---------------------------------------------------------------------------

#define BH    32
#define NSEQ  4096
#define DDIM  64
#define MDIM  266
#define EDIM  64
#define MPAD  272

constexpr float DN_F    = 0.35355339059327373f;  // 64^-0.25
constexpr float DIAG_C  = 0.0625f;               // 0.5 * DN^2
constexpr float EPS_F   = 1e-4f;

// ------------------------------ scratch ------------------------------------
__device__ __align__(16) __nv_bfloat16 g_kb[(size_t)BH * NSEQ * MDIM]; // 69.7MB
__device__ __align__(16) float g_context[BH * MDIM * EDIM];            // ΣE·v
__device__ __align__(16) float g_kmean[BH * MDIM];                     // ΣE
__device__ __align__(16) float g_vsum[BH * EDIM];                      // Σv
__device__ unsigned            g_kmax_u;

__device__ __forceinline__ unsigned fenc(float f) {
    unsigned u = __float_as_uint(f);
    return (u & 0x80000000u) ? ~u : (u | 0x80000000u);
}
__device__ __forceinline__ float fdec(unsigned k) {
    return (k & 0x80000000u) ? __uint_as_float(k ^ 0x80000000u)
                             : __uint_as_float(~k);
}
__device__ __forceinline__ unsigned f2tf(float x) {
    unsigned r;
    asm("cvt.rna.tf32.f32 %0, %1;" : "=r"(r) : "f"(x));
    return r;
}
__device__ __forceinline__ void mma8(float* c, unsigned a0, unsigned a1,
                                     unsigned a2, unsigned a3,
                                     unsigned b0, unsigned b1) {
    asm volatile(
        "mma.sync.aligned.m16n8k8.row.col.f32.tf32.tf32.f32 "
        "{%0,%1,%2,%3}, {%4,%5,%6,%7}, {%8,%9}, {%0,%1,%2,%3};"
        : "+f"(c[0]), "+f"(c[1]), "+f"(c[2]), "+f"(c[3])
        : "r"(a0), "r"(a1), "r"(a2), "r"(a3), "r"(b0), "r"(b1));
}

// 64x64 fp32 -> tf32 tile at row stride S (words). 256 threads.
__device__ __forceinline__ void load_tileS(unsigned* dst, int S,
                                           const float* __restrict__ src,
                                           int valid, int tid) {
#pragma unroll
    for (int t = 0; t < 4; t++) {
        int idx = tid + (t << 8);
        int r = idx >> 4, c4 = (idx & 15) << 2;
        float4 v = (r < valid) ? *(const float4*)(src + (size_t)r * 64 + c4)
                               : make_float4(0.f, 0.f, 0.f, 0.f);
        uint4 u;
        u.x = f2tf(v.x); u.y = f2tf(v.y); u.z = f2tf(v.z); u.w = f2tf(v.w);
        *(uint4*)&dst[r * S + c4] = u;
    }
}
// same (64 valid rows) + DIAG_C * sum(row^2) of ORIGINAL fp32 -> diag_out[r]
__device__ __forceinline__ void load_tile_diagS(unsigned* dst, int S,
                                                const float* __restrict__ src,
                                                int tid, float* diag_out) {
#pragma unroll
    for (int t = 0; t < 4; t++) {
        int idx = tid + (t << 8);
        int r = idx >> 4, c4 = (idx & 15) << 2;
        float4 v = *(const float4*)(src + (size_t)r * 64 + c4);
        float s = v.x * v.x + v.y * v.y + v.z * v.z + v.w * v.w;
        s += __shfl_xor_sync(0xffffffffu, s, 1);
        s += __shfl_xor_sync(0xffffffffu, s, 2);
        s += __shfl_xor_sync(0xffffffffu, s, 4);
        s += __shfl_xor_sync(0xffffffffu, s, 8);
        uint4 u;
        u.x = f2tf(v.x); u.y = f2tf(v.y); u.z = f2tf(v.z); u.w = f2tf(v.w);
        *(uint4*)&dst[r * S + c4] = u;
        if ((tid & 15) == 0) diag_out[r] = DIAG_C * s;
    }
}

// ------------------------------ k0: init -----------------------------------
__global__ void k0_init() {
    int i = blockIdx.x * blockDim.x + threadIdx.x;
    int stride = gridDim.x * blockDim.x;
    if (i == 0) g_kmax_u = 0u;
    for (int t = i; t < BH * MDIM * EDIM; t += stride) g_context[t] = 0.f;
    for (int t = i; t < BH * MDIM; t += stride)        g_kmean[t] = 0.f;
    for (int t = i; t < BH * EDIM; t += stride)        g_vsum[t] = 0.f;
}

// ------------------------------ k1: E = exp(kdash - diag), bf16 ------------
constexpr int K1_KS_W = 128 * 68;
constexpr int K1_PS_W = 64 * 68;
constexpr int K1_WORDS = K1_KS_W + K1_PS_W + 128 + 8;
constexpr int K1_BYTES = K1_WORDS * 4;   // 52,768 B

__global__ __launch_bounds__(256) void k1_kdash(const float* __restrict__ K,
                                                const float* __restrict__ Pm) {
    extern __shared__ __align__(16) unsigned k1s[];
    unsigned* Ks = k1s;                 // [128][68]
    unsigned* Ps = k1s + K1_KS_W;       // [64][68]
    float* diag_s = (float*)(k1s + K1_KS_W + K1_PS_W);   // [128]
    float* red = diag_s + 128;

    int tid = threadIdx.x, lane = tid & 31, warp = tid >> 5;
    int g = lane >> 2, tg = lane & 3;
    int bh = blockIdx.y, n0 = blockIdx.x << 7;
    int nr = (warp >> 1) << 5;
    int cb = (warp & 1) << 5;

    const float* kb = K + ((size_t)bh * NSEQ + n0) * DDIM;
    load_tile_diagS(Ks, 68, kb, tid, diag_s);
    load_tile_diagS(Ks + 64 * 68, 68, kb + (size_t)64 * DDIM, tid, diag_s + 64);

    float lmax = -3.0e38f;
    for (int mc = 0; mc < 5; mc++) {
        int m0 = mc << 6;
        __syncthreads();
        load_tileS(Ps, 68, Pm + (size_t)m0 * DDIM, MDIM - m0, tid);
        __syncthreads();

        float c[2][4][4];
#pragma unroll
        for (int i = 0; i < 2; i++)
#pragma unroll
            for (int j = 0; j < 4; j++)
#pragma unroll
                for (int q = 0; q < 4; q++) c[i][j][q] = 0.f;

#pragma unroll
        for (int ks = 0; ks < 8; ks++) {
            int k0 = ks << 3;
            unsigned a[2][4], b[4][2];
#pragma unroll
            for (int i = 0; i < 2; i++) {
                int r0 = nr + (i << 4);
                a[i][0] = Ks[(r0 + g) * 68 + k0 + tg];
                a[i][1] = Ks[(r0 + g + 8) * 68 + k0 + tg];
                a[i][2] = Ks[(r0 + g) * 68 + k0 + tg + 4];
                a[i][3] = Ks[(r0 + g + 8) * 68 + k0 + tg + 4];
            }
#pragma unroll
            for (int j = 0; j < 4; j++) {
                int mcol = cb + (j << 3) + g;
                b[j][0] = Ps[mcol * 68 + k0 + tg];
                b[j][1] = Ps[mcol * 68 + k0 + tg + 4];
            }
#pragma unroll
            for (int i = 0; i < 2; i++)
#pragma unroll
                for (int j = 0; j < 4; j++)
                    mma8(c[i][j], a[i][0], a[i][1], a[i][2], a[i][3],
                         b[j][0], b[j][1]);
        }

#pragma unroll
        for (int i = 0; i < 2; i++) {
            int rl = nr + (i << 4) + g;
            int row = n0 + rl;
            float dg0 = diag_s[rl], dg1 = diag_s[rl + 8];
#pragma unroll
            for (int j = 0; j < 4; j++) {
                int m = m0 + cb + (j << 3) + (tg << 1);
                if (m < MDIM) {
                    float d0 = c[i][j][0] * DN_F, d1 = c[i][j][1] * DN_F;
                    float d2 = c[i][j][2] * DN_F, d3 = c[i][j][3] * DN_F;
                    lmax = fmaxf(lmax, fmaxf(fmaxf(d0, d1), fmaxf(d2, d3)));
                    __nv_bfloat162 e01 = __floats2bfloat162_rn(
                        __expf(d0 - dg0), __expf(d1 - dg0));
                    __nv_bfloat162 e23 = __floats2bfloat162_rn(
                        __expf(d2 - dg1), __expf(d3 - dg1));
                    *(__nv_bfloat162*)(g_kb +
                        ((size_t)bh * NSEQ + row) * MDIM + m) = e01;
                    *(__nv_bfloat162*)(g_kb +
                        ((size_t)bh * NSEQ + row + 8) * MDIM + m) = e23;
                }
            }
        }
    }

#pragma unroll
    for (int o = 16; o > 0; o >>= 1)
        lmax = fmaxf(lmax, __shfl_xor_sync(0xffffffffu, lmax, o));
    if (lane == 0) red[warp] = lmax;
    __syncthreads();
    if (tid < 8) {
        lmax = red[tid];
        lmax = fmaxf(lmax, __shfl_xor_sync(0xffu, lmax, 1));
        lmax = fmaxf(lmax, __shfl_xor_sync(0xffu, lmax, 2));
        lmax = fmaxf(lmax, __shfl_xor_sync(0xffu, lmax, 4));
        if (tid == 0) atomicMax(&g_kmax_u, fenc(lmax));
    }
}

// ------------------------------ k2: ctx = ΣE·v, km = ΣE, vsum --------------
__global__ __launch_bounds__(256) void k2_context(const float* __restrict__ V) {
    __shared__ __align__(16) unsigned kp_u[64][72];
    __shared__ __align__(16) unsigned v_u[64][72];
    __shared__ float msum_s[64];

    int tid = threadIdx.x, lane = tid & 31, warp = tid >> 5;
    int g = lane >> 2, tg = lane & 3;
    int m0 = blockIdx.x << 6, bh = blockIdx.y, cz = blockIdx.z << 4;
    int mh = (warp & 1) << 5;
    int eb = (warp >> 1) << 4;
    int col = tid & 63, rr = tid >> 6;
    bool cvalid = (m0 + col) < MDIM;
    bool do_vsum = (blockIdx.x == 0);

    if (tid < 64) msum_s[tid] = 0.f;
    float vs_loc = 0.f;

    float acc[2][2][4];
#pragma unroll
    for (int i = 0; i < 2; i++)
#pragma unroll
        for (int j = 0; j < 2; j++)
#pragma unroll
            for (int q = 0; q < 4; q++) acc[i][j][q] = 0.f;

    for (int nc = 0; nc < 16; nc++) {
        int n0 = (cz + nc) << 6;
        __syncthreads();

        const float* vb = V + ((size_t)bh * NSEQ + n0) * EDIM;
#pragma unroll
        for (int t = 0; t < 4; t++) {
            int idx = tid + (t << 8);
            int r = idx >> 4, c4 = (idx & 15) << 2;
            float4 v = *(const float4*)(vb + (size_t)r * 64 + c4);
            uint4 u;
            u.x = f2tf(v.x); u.y = f2tf(v.y); u.z = f2tf(v.z); u.w = f2tf(v.w);
            *(uint4*)&v_u[r][c4] = u;
        }

        const __nv_bfloat16* kdb =
            g_kb + ((size_t)bh * NSEQ + n0) * MDIM + m0 + col;
        float local = 0.f;
#pragma unroll
        for (int t = 0; t < 16; t++) {
            int r = rr + (t << 2);
            float val = cvalid ? __bfloat162float(kdb[(size_t)r * MDIM]) : 0.f;
            kp_u[r][col] = __float_as_uint(val);
            local += val;
        }
        atomicAdd(&msum_s[col], local);
        __syncthreads();

        if (do_vsum) {
            float s = 0.f;
#pragma unroll
            for (int t = 0; t < 16; t++)
                s += __uint_as_float(v_u[rr + (t << 2)][col]);
            vs_loc += s;
        }

#pragma unroll
        for (int ks = 0; ks < 8; ks++) {
            int k0 = ks << 3;
            unsigned a[2][4], b[2][2];
#pragma unroll
            for (int i = 0; i < 2; i++) {
                int mr = mh + (i << 4);
                a[i][0] = kp_u[k0 + tg][mr + g];
                a[i][1] = kp_u[k0 + tg][mr + g + 8];
                a[i][2] = kp_u[k0 + tg + 4][mr + g];
                a[i][3] = kp_u[k0 + tg + 4][mr + g + 8];
            }
#pragma unroll
            for (int j = 0; j < 2; j++) {
                int ec = eb + (j << 3) + g;
                b[j][0] = v_u[k0 + tg][ec];
                b[j][1] = v_u[k0 + tg + 4][ec];
            }
#pragma unroll
            for (int i = 0; i < 2; i++)
#pragma unroll
                for (int j = 0; j < 2; j++)
                    mma8(acc[i][j], a[i][0], a[i][1], a[i][2], a[i][3],
                         b[j][0], b[j][1]);
        }
    }
    __syncthreads();

#pragma unroll
    for (int i = 0; i < 2; i++) {
        int mbase = m0 + mh + (i << 4);
#pragma unroll
        for (int j = 0; j < 2; j++) {
            int e = eb + (j << 3) + (tg << 1);
            int m = mbase + g;
            if (m < MDIM) {
                float* p = g_context + ((size_t)bh * MDIM + m) * EDIM + e;
                atomicAdd(p + 0, acc[i][j][0]);
                atomicAdd(p + 1, acc[i][j][1]);
            }
            if (m + 8 < MDIM) {
                float* p = g_context + ((size_t)bh * MDIM + m + 8) * EDIM + e;
                atomicAdd(p + 0, acc[i][j][2]);
                atomicAdd(p + 1, acc[i][j][3]);
            }
        }
    }
    if (tid < 64 && cvalid)
        atomicAdd(&g_kmean[bh * MDIM + m0 + tid], msum_s[tid]);
    if (do_vsum) atomicAdd(&g_vsum[bh * 64 + col], vs_loc);
}

// ------------------------------ k3: output ---------------------------------
constexpr int SM3_QP_W = MPAD * 72;                // 19584: qp[272][72] tf32 E_q
constexpr int SM3_TQ_W = 64 * 68;                  // 4352: Q tile / OB68 alias
constexpr int SM3_TP_W = 64 * 72;                  // 4608: P(68)/km/ctx(72)
constexpr int SM3_WORDS = SM3_QP_W + SM3_TQ_W + SM3_TP_W + 64 + 64 + 64 + 64;
constexpr int SM3_BYTES = SM3_WORDS * 4;           // 115,200 B (2 CTAs/SM)

__global__ __launch_bounds__(256) void k3_out(const float* __restrict__ Q,
                                              const float* __restrict__ Pm,
                                              float* __restrict__ Out) {
    extern __shared__ __align__(16) unsigned smu[];
    unsigned* qp    = smu;                               // tf32 E_q, stride 72
    unsigned* TQ68  = smu + SM3_QP_W;                    // [64][68]
    float*    OB68  = (float*)TQ68;                      // phase-3 reduce buffer
    unsigned* TP    = smu + SM3_QP_W + SM3_TQ_W;         // P tile / km / ctx
    float*    km    = (float*)TP;                        // phase-2b alias
    unsigned* wmaxu = smu + SM3_QP_W + SM3_TQ_W + SM3_TP_W; // fenc row max
    float*    dq    = (float*)(wmaxu + 64);
    float*    dinv  = dq + 64;
    float*    Ssum  = dinv + 64;

    int tid = threadIdx.x, lane = tid & 31, warp = tid >> 5;
    int g = lane >> 2, tg = lane & 3;
    int bh = blockIdx.y, n0 = blockIdx.x << 6;
    int rb = (warp & 1) << 5;      // phase-1 n slab
    int cb = (warp >> 1) << 4;     // phase-1 m slab

    float epsp = EPS_F * __expf(fdec(g_kmax_u));   // eps' = eps * e^s
    float4 vs4 = *(const float4*)(g_vsum + bh * 64 + ((tid & 15) << 2));
    vs4.x *= epsp; vs4.y *= epsp; vs4.z *= epsp; vs4.w *= epsp;

    load_tile_diagS(TQ68, 68, Q + ((size_t)bh * NSEQ + n0) * DDIM, tid, dq);
    if (tid < 64) wmaxu[tid] = 0u;

    // ---- phase 1: mma q@P^T -> E_q = exp(d - diag) -> tf32 qp[m][r] ----
    float rmax[2][2] = {{-3.0e38f, -3.0e38f}, {-3.0e38f, -3.0e38f}};
    for (int mc = 0; mc < 5; mc++) {
        int m0 = mc << 6;
        __syncthreads();
        load_tileS(TP, 68, Pm + (size_t)m0 * DDIM, MDIM - m0, tid);
        __syncthreads();

        float c[2][2][4];
#pragma unroll
        for (int i = 0; i < 2; i++)
#pragma unroll
            for (int j = 0; j < 2; j++)
#pragma unroll
                for (int q = 0; q < 4; q++) c[i][j][q] = 0.f;

#pragma unroll
        for (int ks = 0; ks < 8; ks++) {
            int k0 = ks << 3;
            unsigned a[2][4], b[2][2];
#pragma unroll
            for (int i = 0; i < 2; i++) {
                int r0 = rb + (i << 4);
                a[i][0] = TQ68[(r0 + g) * 68 + k0 + tg];
                a[i][1] = TQ68[(r0 + g + 8) * 68 + k0 + tg];
                a[i][2] = TQ68[(r0 + g) * 68 + k0 + tg + 4];
                a[i][3] = TQ68[(r0 + g + 8) * 68 + k0 + tg + 4];
            }
#pragma unroll
            for (int j = 0; j < 2; j++) {
                int mcol = cb + (j << 3) + g;
                b[j][0] = TP[mcol * 68 + k0 + tg];
                b[j][1] = TP[mcol * 68 + k0 + tg + 4];
            }
#pragma unroll
            for (int i = 0; i < 2; i++)
#pragma unroll
                for (int j = 0; j < 2; j++)
                    mma8(c[i][j], a[i][0], a[i][1], a[i][2], a[i][3],
                         b[j][0], b[j][1]);
        }
#pragma unroll
        for (int i = 0; i < 2; i++) {
            int r = rb + (i << 4) + g;
            float dg0 = dq[r], dg1 = dq[r + 8];
#pragma unroll
            for (int j = 0; j < 2; j++) {
                int m = m0 + cb + (j << 3) + (tg << 1);
                if (m < MDIM) {
                    float d0 = c[i][j][0] * DN_F, d1 = c[i][j][1] * DN_F;
                    float d2 = c[i][j][2] * DN_F, d3 = c[i][j][3] * DN_F;
                    rmax[i][0] = fmaxf(rmax[i][0], fmaxf(d0, d1));
                    rmax[i][1] = fmaxf(rmax[i][1], fmaxf(d2, d3));
                    qp[m * 72 + r]           = f2tf(__expf(d0 - dg0));
                    qp[(m + 1) * 72 + r]     = f2tf(__expf(d1 - dg0));
                    qp[m * 72 + r + 8]       = f2tf(__expf(d2 - dg1));
                    qp[(m + 1) * 72 + r + 8] = f2tf(__expf(d3 - dg1));
                }
            }
        }
    }
#pragma unroll
    for (int i = 0; i < 2; i++)
#pragma unroll
        for (int h = 0; h < 2; h++) {
            float v = rmax[i][h];
            v = fmaxf(v, __shfl_xor_sync(0xffffffffu, v, 1));
            v = fmaxf(v, __shfl_xor_sync(0xffffffffu, v, 2));
            if (tg == 0)
                atomicMax(&wmaxu[rb + (i << 4) + g + (h << 3)], fenc(v));
        }
    __syncthreads();   // qp + wmaxu complete; P tile dead

    // ---- phase 2b: km load, dsum = ΣE_q·KM, kms = ΣKM, dinv ----
    for (int i = tid; i < MDIM; i += 256)
        km[i] = g_kmean[bh * MDIM + i] + 4096.0f * epsp;   // KM = ΣE + L*eps'
    if (tid < 64) Ssum[tid] = 0.f;
    for (int idx = tid; idx < 6 * 72; idx += 256)          // zero pad rows
        qp[MDIM * 72 + idx] = 0u;
    __syncthreads();
    {
        int r = tid >> 2, g4 = tid & 3;
        float dsum = 0.f, kms = 0.f;
        for (int cc = g4; cc < MDIM; cc += 4) {
            float kv = km[cc];
            dsum = fmaf(__uint_as_float(qp[cc * 72 + r]), kv, dsum);
            kms += kv;
        }
        dsum += __shfl_xor_sync(0xffffffffu, dsum, 1);
        dsum += __shfl_xor_sync(0xffffffffu, dsum, 2);
        kms  += __shfl_xor_sync(0xffffffffu, kms, 1);
        kms  += __shfl_xor_sync(0xffffffffu, kms, 2);
        if (g4 == 0) {
            float epsr = EPS_F * __expf(fdec(wmaxu[r]));
            dinv[r] = 1.0f / fmaf(epsr, kms, dsum);
        }
    }

    // ---- phase 3: out = (E_q @ CTX + εr·S)·dinv, split-k warp pairs ----
    int sub = warp >> 2;
    int wg  = warp & 3;
    int rb2 = (wg & 1) << 5;
    int eb2 = (wg >> 1) << 5;

    float c[2][4][4];
#pragma unroll
    for (int i = 0; i < 2; i++)
#pragma unroll
        for (int j = 0; j < 4; j++)
#pragma unroll
            for (int q = 0; q < 4; q++) c[i][j][q] = 0.f;

    float4 sS = make_float4(0.f, 0.f, 0.f, 0.f);
    for (int kc = 0; kc < 5; kc++) {
        int k00 = kc << 6;
        int half = (kc < 4) ? 4 : 1;
        __syncthreads();
        {   // ctx tile + eps'*vsum correction; accumulate column sums S
            const float* cbp = g_context + ((size_t)bh * MDIM + k00) * EDIM;
            int valid = MDIM - k00;
            int c4 = (tid & 15) << 2;
#pragma unroll
            for (int t = 0; t < 4; t++) {
                int r = (tid + (t << 8)) >> 4;
                float4 v = make_float4(0.f, 0.f, 0.f, 0.f);
                if (r < valid) {
                    v = *(const float4*)(cbp + (size_t)r * 64 + c4);
                    v.x += vs4.x; v.y += vs4.y; v.z += vs4.z; v.w += vs4.w;
                    sS.x += v.x; sS.y += v.y; sS.z += v.z; sS.w += v.w;
                }
                uint4 u;
                u.x = f2tf(v.x); u.y = f2tf(v.y);
                u.z = f2tf(v.z); u.w = f2tf(v.w);
                *(uint4*)&TP[r * 72 + c4] = u;
            }
        }
        __syncthreads();

        int ks0 = sub * half, ks1 = ks0 + half;
        for (int ks = ks0; ks < ks1; ks++) {
            int kl = ks << 3;
            unsigned a[2][4], b[4][2];
#pragma unroll
            for (int i = 0; i < 2; i++) {
                int r0 = rb2 + (i << 4);
                a[i][0] = qp[(k00 + kl + tg) * 72 + r0 + g];
                a[i][1] = qp[(k00 + kl + tg) * 72 + r0 + g + 8];
                a[i][2] = qp[(k00 + kl + tg + 4) * 72 + r0 + g];
                a[i][3] = qp[(k00 + kl + tg + 4) * 72 + r0 + g + 8];
            }
#pragma unroll
            for (int j = 0; j < 4; j++) {
                int ec = eb2 + (j << 3) + g;
                b[j][0] = TP[(kl + tg) * 72 + ec];
                b[j][1] = TP[(kl + tg + 4) * 72 + ec];
            }
#pragma unroll
            for (int i = 0; i < 2; i++)
#pragma unroll
                for (int j = 0; j < 4; j++)
                    mma8(c[i][j], a[i][0], a[i][1], a[i][2], a[i][3],
                         b[j][0], b[j][1]);
        }
    }

    // column sums S[e] = Σ_m CTX[m][e]
    {
        int c4 = (tid & 15) << 2;
        atomicAdd(&Ssum[c4 + 0], sS.x);
        atomicAdd(&Ssum[c4 + 1], sS.y);
        atomicAdd(&Ssum[c4 + 2], sS.z);
        atomicAdd(&Ssum[c4 + 3], sS.w);
    }
    __syncthreads();
    if (sub == 0) {
#pragma unroll
        for (int i = 0; i < 2; i++) {
            int row = rb2 + (i << 4) + g;
#pragma unroll
            for (int j = 0; j < 4; j++) {
                int col = eb2 + (j << 3) + (tg << 1);
                OB68[row * 68 + col]           = c[i][j][0];
                OB68[row * 68 + col + 1]       = c[i][j][1];
                OB68[(row + 8) * 68 + col]     = c[i][j][2];
                OB68[(row + 8) * 68 + col + 1] = c[i][j][3];
            }
        }
    }
    __syncthreads();
    if (sub == 1) {
#pragma unroll
        for (int i = 0; i < 2; i++) {
            int row = rb2 + (i << 4) + g;
            float d0 = dinv[row], d1 = dinv[row + 8];
            float er0 = EPS_F * __expf(fdec(wmaxu[row]));
            float er1 = EPS_F * __expf(fdec(wmaxu[row + 8]));
#pragma unroll
            for (int j = 0; j < 4; j++) {
                int col = eb2 + (j << 3) + (tg << 1);
                float s0 = Ssum[col], s1 = Ssum[col + 1];
                float2 v0, v1;
                v0.x = (c[i][j][0] + OB68[row * 68 + col]       + er0 * s0) * d0;
                v0.y = (c[i][j][1] + OB68[row * 68 + col + 1]   + er0 * s1) * d0;
                v1.x = (c[i][j][2] + OB68[(row + 8) * 68 + col] + er1 * s0) * d1;
                v1.y = (c[i][j][3] + OB68[(row + 8) * 68 + col + 1] + er1 * s1) * d1;
                *(float2*)(Out + ((size_t)bh * NSEQ + n0 + row) * EDIM + col)     = v0;
                *(float2*)(Out + ((size_t)bh * NSEQ + n0 + row + 8) * EDIM + col) = v1;
            }
        }
    }
}

// ------------------------------ launch -------------------------------------
extern "C" void kernel_launch(void* const* d_in, const int* in_sizes, int n_in,
                              void* d_out, int out_size) {
    const float* q = (const float*)d_in[0];
    const float* k = (const float*)d_in[1];
    const float* v = (const float*)d_in[2];
    const float* P = (const float*)d_in[3];
    float* out = (float*)d_out;

    cudaFuncSetAttribute(k1_kdash, cudaFuncAttributeMaxDynamicSharedMemorySize,
                         K1_BYTES);
    cudaFuncSetAttribute(k3_out, cudaFuncAttributeMaxDynamicSharedMemorySize,
                         SM3_BYTES);

    k0_init<<<256, 256>>>();
    k1_kdash<<<dim3(NSEQ / 128, BH), 256, K1_BYTES>>>(k, P);
    k2_context<<<dim3(5, BH, 4), 256>>>(v);
    k3_out<<<dim3(NSEQ / 64, BH), 256, SM3_BYTES>>>(q, P, out);
}

// round 12
// speedup vs baseline: 1.0628x; 1.0628x over previous
#include <cuda_runtime.h>
#include <cuda_bf16.h>
#include <cstdint>

// ---------------------------------------------------------------------------
// FastAttention (Performer / FAVOR+) — TF32 warp-MMA, stab-cancelled (R9 base)
//   b=4, h=8 (BH=32), n=4096, d=64, m=266, e=64
//   k1: E = exp(dn*k@P^T - diag) UNSTABBED, bf16; s = max(d)
//   k2: ctx = ΣE·v (tf32 mma), km = ΣE, vsum = Σv
//   k3: EPS'=EPS*e^s; CTX = ctx + EPS'·vsum; KM = km + L·EPS'
// R12 change: A-fragments (K rows / Q rows) hoisted into 64 registers across
//   the 5-tile m-loop (A tile is loop-invariant) — removes 2/3 of phase LDS
//   + its address ALU. __launch_bounds__(256,2) pins regs <= 128.
// Bank rules: g-rows stride 68; tg-rows stride 72 (words).
// SMEM CLIFF: k3 <= 115,712 B for 2 CTAs/SM (this build: exactly 115,712).
// ---------------------------------------------------------------------------

#define BH    32
#define NSEQ  4096
#define DDIM  64
#define MDIM  266
#define EDIM  64
#define MPAD  272

constexpr float DN_F    = 0.35355339059327373f;  // 64^-0.25
constexpr float DIAG_C  = 0.0625f;               // 0.5 * DN^2
constexpr float RATIO_F = 0.06131393316f;        // 266^-0.5
constexpr float EPS_F   = 1e-4f;

// ------------------------------ scratch ------------------------------------
__device__ __align__(16) __nv_bfloat16 g_kb[(size_t)BH * NSEQ * MDIM]; // 69.7MB
__device__ __align__(16) float g_context[BH * MDIM * EDIM];            // ΣE·v
__device__ __align__(16) float g_kmean[BH * MDIM];                     // ΣE
__device__ __align__(16) float g_vsum[BH * EDIM];                      // Σv
__device__ unsigned            g_kmax_u;

__device__ __forceinline__ unsigned fenc(float f) {
    unsigned u = __float_as_uint(f);
    return (u & 0x80000000u) ? ~u : (u | 0x80000000u);
}
__device__ __forceinline__ float fdec(unsigned k) {
    return (k & 0x80000000u) ? __uint_as_float(k ^ 0x80000000u)
                             : __uint_as_float(~k);
}
__device__ __forceinline__ unsigned f2tf(float x) {
    unsigned r;
    asm("cvt.rna.tf32.f32 %0, %1;" : "=r"(r) : "f"(x));
    return r;
}
__device__ __forceinline__ void mma8(float* c, unsigned a0, unsigned a1,
                                     unsigned a2, unsigned a3,
                                     unsigned b0, unsigned b1) {
    asm volatile(
        "mma.sync.aligned.m16n8k8.row.col.f32.tf32.tf32.f32 "
        "{%0,%1,%2,%3}, {%4,%5,%6,%7}, {%8,%9}, {%0,%1,%2,%3};"
        : "+f"(c[0]), "+f"(c[1]), "+f"(c[2]), "+f"(c[3])
        : "r"(a0), "r"(a1), "r"(a2), "r"(a3), "r"(b0), "r"(b1));
}

// 64x64 fp32 -> tf32 tile at row stride S (words). 256 threads.
__device__ __forceinline__ void load_tileS(unsigned* dst, int S,
                                           const float* __restrict__ src,
                                           int valid, int tid) {
#pragma unroll
    for (int t = 0; t < 4; t++) {
        int idx = tid + (t << 8);
        int r = idx >> 4, c4 = (idx & 15) << 2;
        float4 v = (r < valid) ? *(const float4*)(src + (size_t)r * 64 + c4)
                               : make_float4(0.f, 0.f, 0.f, 0.f);
        uint4 u;
        u.x = f2tf(v.x); u.y = f2tf(v.y); u.z = f2tf(v.z); u.w = f2tf(v.w);
        *(uint4*)&dst[r * S + c4] = u;
    }
}
// same (64 valid rows) + DIAG_C * sum(row^2) of ORIGINAL fp32 -> diag_out[r]
__device__ __forceinline__ void load_tile_diagS(unsigned* dst, int S,
                                                const float* __restrict__ src,
                                                int tid, float* diag_out) {
#pragma unroll
    for (int t = 0; t < 4; t++) {
        int idx = tid + (t << 8);
        int r = idx >> 4, c4 = (idx & 15) << 2;
        float4 v = *(const float4*)(src + (size_t)r * 64 + c4);
        float s = v.x * v.x + v.y * v.y + v.z * v.z + v.w * v.w;
        s += __shfl_xor_sync(0xffffffffu, s, 1);
        s += __shfl_xor_sync(0xffffffffu, s, 2);
        s += __shfl_xor_sync(0xffffffffu, s, 4);
        s += __shfl_xor_sync(0xffffffffu, s, 8);
        uint4 u;
        u.x = f2tf(v.x); u.y = f2tf(v.y); u.z = f2tf(v.z); u.w = f2tf(v.w);
        *(uint4*)&dst[r * S + c4] = u;
        if ((tid & 15) == 0) diag_out[r] = DIAG_C * s;
    }
}

// ------------------------------ k0: init -----------------------------------
__global__ void k0_init() {
    int i = blockIdx.x * blockDim.x + threadIdx.x;
    int stride = gridDim.x * blockDim.x;
    if (i == 0) g_kmax_u = 0u;
    for (int t = i; t < BH * MDIM * EDIM; t += stride) g_context[t] = 0.f;
    for (int t = i; t < BH * MDIM; t += stride)        g_kmean[t] = 0.f;
    for (int t = i; t < BH * EDIM; t += stride)        g_vsum[t] = 0.f;
}

// ------------------------------ k1: E = exp(kdash - diag), bf16 ------------
constexpr int K1_KS_W = 128 * 68;
constexpr int K1_PS_W = 64 * 68;
constexpr int K1_WORDS = K1_KS_W + K1_PS_W + 128 + 8;
constexpr int K1_BYTES = K1_WORDS * 4;   // 52,768 B

__global__ __launch_bounds__(256, 2) void k1_kdash(const float* __restrict__ K,
                                                   const float* __restrict__ Pm) {
    extern __shared__ __align__(16) unsigned k1s[];
    unsigned* Ks = k1s;                 // [128][68]
    unsigned* Ps = k1s + K1_KS_W;       // [64][68]
    float* diag_s = (float*)(k1s + K1_KS_W + K1_PS_W);   // [128]
    float* red = diag_s + 128;

    int tid = threadIdx.x, lane = tid & 31, warp = tid >> 5;
    int g = lane >> 2, tg = lane & 3;
    int bh = blockIdx.y, n0 = blockIdx.x << 7;
    int nr = (warp >> 1) << 5;
    int cb = (warp & 1) << 5;

    const float* kb = K + ((size_t)bh * NSEQ + n0) * DDIM;
    load_tile_diagS(Ks, 68, kb, tid, diag_s);
    load_tile_diagS(Ks + 64 * 68, 68, kb + (size_t)64 * DDIM, tid, diag_s + 64);
    __syncthreads();

    // hoist A (K) fragments — loop-invariant across all 5 m-tiles
    unsigned ak[2][8][4];
#pragma unroll
    for (int ks = 0; ks < 8; ks++) {
        int k0 = ks << 3;
#pragma unroll
        for (int i = 0; i < 2; i++) {
            int r0 = nr + (i << 4);
            ak[i][ks][0] = Ks[(r0 + g) * 68 + k0 + tg];
            ak[i][ks][1] = Ks[(r0 + g + 8) * 68 + k0 + tg];
            ak[i][ks][2] = Ks[(r0 + g) * 68 + k0 + tg + 4];
            ak[i][ks][3] = Ks[(r0 + g + 8) * 68 + k0 + tg + 4];
        }
    }

    float lmax = -3.0e38f;
    for (int mc = 0; mc < 5; mc++) {
        int m0 = mc << 6;
        __syncthreads();
        load_tileS(Ps, 68, Pm + (size_t)m0 * DDIM, MDIM - m0, tid);
        __syncthreads();

        float c[2][4][4];
#pragma unroll
        for (int i = 0; i < 2; i++)
#pragma unroll
            for (int j = 0; j < 4; j++)
#pragma unroll
                for (int q = 0; q < 4; q++) c[i][j][q] = 0.f;

#pragma unroll
        for (int ks = 0; ks < 8; ks++) {
            int k0 = ks << 3;
            unsigned b[4][2];
#pragma unroll
            for (int j = 0; j < 4; j++) {
                int mcol = cb + (j << 3) + g;
                b[j][0] = Ps[mcol * 68 + k0 + tg];
                b[j][1] = Ps[mcol * 68 + k0 + tg + 4];
            }
#pragma unroll
            for (int i = 0; i < 2; i++)
#pragma unroll
                for (int j = 0; j < 4; j++)
                    mma8(c[i][j], ak[i][ks][0], ak[i][ks][1],
                         ak[i][ks][2], ak[i][ks][3], b[j][0], b[j][1]);
        }

#pragma unroll
        for (int i = 0; i < 2; i++) {
            int rl = nr + (i << 4) + g;
            int row = n0 + rl;
            float dg0 = diag_s[rl], dg1 = diag_s[rl + 8];
#pragma unroll
            for (int j = 0; j < 4; j++) {
                int m = m0 + cb + (j << 3) + (tg << 1);
                if (m < MDIM) {
                    float d0 = c[i][j][0] * DN_F, d1 = c[i][j][1] * DN_F;
                    float d2 = c[i][j][2] * DN_F, d3 = c[i][j][3] * DN_F;
                    lmax = fmaxf(lmax, fmaxf(fmaxf(d0, d1), fmaxf(d2, d3)));
                    __nv_bfloat162 e01 = __floats2bfloat162_rn(
                        __expf(d0 - dg0), __expf(d1 - dg0));
                    __nv_bfloat162 e23 = __floats2bfloat162_rn(
                        __expf(d2 - dg1), __expf(d3 - dg1));
                    *(__nv_bfloat162*)(g_kb +
                        ((size_t)bh * NSEQ + row) * MDIM + m) = e01;
                    *(__nv_bfloat162*)(g_kb +
                        ((size_t)bh * NSEQ + row + 8) * MDIM + m) = e23;
                }
            }
        }
    }

#pragma unroll
    for (int o = 16; o > 0; o >>= 1)
        lmax = fmaxf(lmax, __shfl_xor_sync(0xffffffffu, lmax, o));
    if (lane == 0) red[warp] = lmax;
    __syncthreads();
    if (tid < 8) {
        lmax = red[tid];
        lmax = fmaxf(lmax, __shfl_xor_sync(0xffu, lmax, 1));
        lmax = fmaxf(lmax, __shfl_xor_sync(0xffu, lmax, 2));
        lmax = fmaxf(lmax, __shfl_xor_sync(0xffu, lmax, 4));
        if (tid == 0) atomicMax(&g_kmax_u, fenc(lmax));
    }
}

// ------------------------------ k2: ctx = ΣE·v, km = ΣE, vsum --------------
__global__ __launch_bounds__(256) void k2_context(const float* __restrict__ V) {
    __shared__ __align__(16) unsigned kp_u[64][72];
    __shared__ __align__(16) unsigned v_u[64][72];
    __shared__ float msum_s[64];

    int tid = threadIdx.x, lane = tid & 31, warp = tid >> 5;
    int g = lane >> 2, tg = lane & 3;
    int m0 = blockIdx.x << 6, bh = blockIdx.y, cz = blockIdx.z << 4;
    int mh = (warp & 1) << 5;
    int eb = (warp >> 1) << 4;
    int col = tid & 63, rr = tid >> 6;
    bool cvalid = (m0 + col) < MDIM;
    bool do_vsum = (blockIdx.x == 0);

    if (tid < 64) msum_s[tid] = 0.f;
    float vs_loc = 0.f;

    float acc[2][2][4];
#pragma unroll
    for (int i = 0; i < 2; i++)
#pragma unroll
        for (int j = 0; j < 2; j++)
#pragma unroll
            for (int q = 0; q < 4; q++) acc[i][j][q] = 0.f;

    for (int nc = 0; nc < 16; nc++) {
        int n0 = (cz + nc) << 6;
        __syncthreads();

        const float* vb = V + ((size_t)bh * NSEQ + n0) * EDIM;
#pragma unroll
        for (int t = 0; t < 4; t++) {
            int idx = tid + (t << 8);
            int r = idx >> 4, c4 = (idx & 15) << 2;
            float4 v = *(const float4*)(vb + (size_t)r * 64 + c4);
            uint4 u;
            u.x = f2tf(v.x); u.y = f2tf(v.y); u.z = f2tf(v.z); u.w = f2tf(v.w);
            *(uint4*)&v_u[r][c4] = u;
        }

        const __nv_bfloat16* kdb =
            g_kb + ((size_t)bh * NSEQ + n0) * MDIM + m0 + col;
        float local = 0.f;
#pragma unroll
        for (int t = 0; t < 16; t++) {
            int r = rr + (t << 2);
            float val = cvalid ? __bfloat162float(kdb[(size_t)r * MDIM]) : 0.f;
            kp_u[r][col] = __float_as_uint(val);
            local += val;
        }
        atomicAdd(&msum_s[col], local);
        __syncthreads();

        if (do_vsum) {
            float s = 0.f;
#pragma unroll
            for (int t = 0; t < 16; t++)
                s += __uint_as_float(v_u[rr + (t << 2)][col]);
            vs_loc += s;
        }

#pragma unroll
        for (int ks = 0; ks < 8; ks++) {
            int k0 = ks << 3;
            unsigned a[2][4], b[2][2];
#pragma unroll
            for (int i = 0; i < 2; i++) {
                int mr = mh + (i << 4);
                a[i][0] = kp_u[k0 + tg][mr + g];
                a[i][1] = kp_u[k0 + tg][mr + g + 8];
                a[i][2] = kp_u[k0 + tg + 4][mr + g];
                a[i][3] = kp_u[k0 + tg + 4][mr + g + 8];
            }
#pragma unroll
            for (int j = 0; j < 2; j++) {
                int ec = eb + (j << 3) + g;
                b[j][0] = v_u[k0 + tg][ec];
                b[j][1] = v_u[k0 + tg + 4][ec];
            }
#pragma unroll
            for (int i = 0; i < 2; i++)
#pragma unroll
                for (int j = 0; j < 2; j++)
                    mma8(acc[i][j], a[i][0], a[i][1], a[i][2], a[i][3],
                         b[j][0], b[j][1]);
        }
    }
    __syncthreads();

#pragma unroll
    for (int i = 0; i < 2; i++) {
        int mbase = m0 + mh + (i << 4);
#pragma unroll
        for (int j = 0; j < 2; j++) {
            int e = eb + (j << 3) + (tg << 1);
            int m = mbase + g;
            if (m < MDIM) {
                float* p = g_context + ((size_t)bh * MDIM + m) * EDIM + e;
                atomicAdd(p + 0, acc[i][j][0]);
                atomicAdd(p + 1, acc[i][j][1]);
            }
            if (m + 8 < MDIM) {
                float* p = g_context + ((size_t)bh * MDIM + m + 8) * EDIM + e;
                atomicAdd(p + 0, acc[i][j][2]);
                atomicAdd(p + 1, acc[i][j][3]);
            }
        }
    }
    if (tid < 64 && cvalid)
        atomicAdd(&g_kmean[bh * MDIM + m0 + tid], msum_s[tid]);
    if (do_vsum) atomicAdd(&g_vsum[bh * 64 + col], vs_loc);
}

// ------------------------------ k3: output ---------------------------------
// vsum in registers; SM3_BYTES exactly 115,712 (the 2-CTA/SM cliff).
constexpr int SM3_QP_W = MPAD * 72;                // 19584: qp[272][72]
constexpr int SM3_TQ_W = 64 * 68;                  // 4352: Q tile / obuf alias
constexpr int SM3_TP_W = 64 * 72;                  // 4608: P(68)/context(72)/km
constexpr int SM3_WMAX = 4 * 64;                   // 256
constexpr int SM3_WORDS = SM3_QP_W + SM3_TQ_W + SM3_TP_W + SM3_WMAX + 64 + 64;
constexpr int SM3_BYTES = SM3_WORDS * 4;           // 115,712 B (2 CTAs/SM)

__global__ __launch_bounds__(256, 2) void k3_out(const float* __restrict__ Q,
                                                 const float* __restrict__ Pm,
                                                 float* __restrict__ Out) {
    extern __shared__ __align__(16) unsigned smu[];
    unsigned* qp   = smu;                               // stride 72
    unsigned* TQ68 = smu + SM3_QP_W;                    // [64][68]
    float*    OB68 = (float*)TQ68;                      // phase-3 reduce buffer
    unsigned* TP   = smu + SM3_QP_W + SM3_TQ_W;         // [64][68] or [64][72]
    float*    km   = (float*)TP;                        // phase-2 alias
    float*    wmax = (float*)(smu + SM3_QP_W + SM3_TQ_W + SM3_TP_W);
    float*    dq   = wmax + SM3_WMAX;
    float*    dinv = dq + 64;

    int tid = threadIdx.x, lane = tid & 31, warp = tid >> 5;
    int g = lane >> 2, tg = lane & 3;
    int bh = blockIdx.y, n0 = blockIdx.x << 6;
    int rb = (warp & 1) << 5;      // phase-1 n slab
    int cb = (warp >> 1) << 4;     // phase-1 m slab

    float epsp = EPS_F * __expf(fdec(g_kmax_u));   // EPS' = EPS * e^stab
    float4 vs4 = *(const float4*)(g_vsum + bh * 64 + ((tid & 15) << 2));
    vs4.x *= epsp; vs4.y *= epsp; vs4.z *= epsp; vs4.w *= epsp;

    load_tile_diagS(TQ68, 68, Q + ((size_t)bh * NSEQ + n0) * DDIM, tid, dq);
    __syncthreads();

    // hoist A (Q) fragments — loop-invariant across all 5 m-tiles
    unsigned aq[2][8][4];
#pragma unroll
    for (int ks = 0; ks < 8; ks++) {
        int k0 = ks << 3;
#pragma unroll
        for (int i = 0; i < 2; i++) {
            int r0 = rb + (i << 4);
            aq[i][ks][0] = TQ68[(r0 + g) * 68 + k0 + tg];
            aq[i][ks][1] = TQ68[(r0 + g + 8) * 68 + k0 + tg];
            aq[i][ks][2] = TQ68[(r0 + g) * 68 + k0 + tg + 4];
            aq[i][ks][3] = TQ68[(r0 + g + 8) * 68 + k0 + tg + 4];
        }
    }

    // ---- phase 1: q_dash -> qp[m][r] raw fp32; row-max in registers ----
    float rmax[2][2] = {{-3.0e38f, -3.0e38f}, {-3.0e38f, -3.0e38f}};
    for (int mc = 0; mc < 5; mc++) {
        int m0 = mc << 6;
        __syncthreads();
        load_tileS(TP, 68, Pm + (size_t)m0 * DDIM, MDIM - m0, tid);
        __syncthreads();

        float c[2][2][4];
#pragma unroll
        for (int i = 0; i < 2; i++)
#pragma unroll
            for (int j = 0; j < 2; j++)
#pragma unroll
                for (int q = 0; q < 4; q++) c[i][j][q] = 0.f;

#pragma unroll
        for (int ks = 0; ks < 8; ks++) {
            int k0 = ks << 3;
            unsigned b[2][2];
#pragma unroll
            for (int j = 0; j < 2; j++) {
                int mcol = cb + (j << 3) + g;
                b[j][0] = TP[mcol * 68 + k0 + tg];
                b[j][1] = TP[mcol * 68 + k0 + tg + 4];
            }
#pragma unroll
            for (int i = 0; i < 2; i++)
#pragma unroll
                for (int j = 0; j < 2; j++)
                    mma8(c[i][j], aq[i][ks][0], aq[i][ks][1],
                         aq[i][ks][2], aq[i][ks][3], b[j][0], b[j][1]);
        }
#pragma unroll
        for (int i = 0; i < 2; i++) {
            int r = rb + (i << 4) + g;
#pragma unroll
            for (int j = 0; j < 2; j++) {
                int m = m0 + cb + (j << 3) + (tg << 1);
                if (m < MDIM) {
                    float v0 = c[i][j][0] * DN_F, v1 = c[i][j][1] * DN_F;
                    float v2 = c[i][j][2] * DN_F, v3 = c[i][j][3] * DN_F;
                    qp[m * 72 + r]           = __float_as_uint(v0);
                    qp[(m + 1) * 72 + r]     = __float_as_uint(v1);
                    qp[m * 72 + r + 8]       = __float_as_uint(v2);
                    qp[(m + 1) * 72 + r + 8] = __float_as_uint(v3);
                    rmax[i][0] = fmaxf(rmax[i][0], fmaxf(v0, v1));
                    rmax[i][1] = fmaxf(rmax[i][1], fmaxf(v2, v3));
                }
            }
        }
    }
#pragma unroll
    for (int i = 0; i < 2; i++)
#pragma unroll
        for (int h = 0; h < 2; h++) {
            float v = rmax[i][h];
            v = fmaxf(v, __shfl_xor_sync(0xffffffffu, v, 1));
            v = fmaxf(v, __shfl_xor_sync(0xffffffffu, v, 2));
            if (tg == 0)
                wmax[(warp >> 1) * 64 + rb + (i << 4) + g + (h << 3)] = v;
        }
    for (int i = tid; i < MDIM; i += 256)
        km[i] = g_kmean[bh * MDIM + i] + 4096.0f * epsp;   // KM = ΣE + L*EPS'
    __syncthreads();

    // ---- phase 2: exp + D_inv ----
    {
        int r = tid >> 2, g4 = tid & 3;
        float mx = fmaxf(fmaxf(wmax[r], wmax[64 + r]),
                         fmaxf(wmax[128 + r], wmax[192 + r]));
        float dqr = dq[r];
        float dsum = 0.f;
        for (int cc = g4; cc < MDIM; cc += 4) {
            float val = RATIO_F *
                (__expf(__uint_as_float(qp[cc * 72 + r]) - dqr - mx) + EPS_F);
            qp[cc * 72 + r] = f2tf(val);
            dsum += val * km[cc];
        }
        dsum += __shfl_xor_sync(0xffffffffu, dsum, 1);
        dsum += __shfl_xor_sync(0xffffffffu, dsum, 2);
        if (g4 == 0) dinv[r] = 1.0f / dsum;
    }

    // ---- phase 3: out = (qp @ CTX) * dinv, split-k warp pairs ----
    int sub = warp >> 2;
    int wg  = warp & 3;
    int rb2 = (wg & 1) << 5;
    int eb2 = (wg >> 1) << 5;

    float c[2][4][4];
#pragma unroll
    for (int i = 0; i < 2; i++)
#pragma unroll
        for (int j = 0; j < 4; j++)
#pragma unroll
            for (int q = 0; q < 4; q++) c[i][j][q] = 0.f;

    for (int kc = 0; kc < 5; kc++) {
        int k00 = kc << 6;
        int half = (kc < 4) ? 4 : 1;
        __syncthreads();
        {   // context tile + EPS'*vsum correction (vs4 registers)
            const float* cbp = g_context + ((size_t)bh * MDIM + k00) * EDIM;
            int valid = MDIM - k00;
            int c4 = (tid & 15) << 2;
#pragma unroll
            for (int t = 0; t < 4; t++) {
                int idx = tid + (t << 8);
                int r = idx >> 4;
                float4 v = make_float4(0.f, 0.f, 0.f, 0.f);
                if (r < valid) {
                    v = *(const float4*)(cbp + (size_t)r * 64 + c4);
                    v.x += vs4.x; v.y += vs4.y; v.z += vs4.z; v.w += vs4.w;
                }
                uint4 u;
                u.x = f2tf(v.x); u.y = f2tf(v.y);
                u.z = f2tf(v.z); u.w = f2tf(v.w);
                *(uint4*)&TP[r * 72 + c4] = u;
            }
        }
        __syncthreads();

        int ks0 = sub * half, ks1 = ks0 + half;
        for (int ks = ks0; ks < ks1; ks++) {
            int kl = ks << 3;
            unsigned a[2][4], b[4][2];
#pragma unroll
            for (int i = 0; i < 2; i++) {
                int r0 = rb2 + (i << 4);
                a[i][0] = qp[(k00 + kl + tg) * 72 + r0 + g];
                a[i][1] = qp[(k00 + kl + tg) * 72 + r0 + g + 8];
                a[i][2] = qp[(k00 + kl + tg + 4) * 72 + r0 + g];
                a[i][3] = qp[(k00 + kl + tg + 4) * 72 + r0 + g + 8];
            }
#pragma unroll
            for (int j = 0; j < 4; j++) {
                int ec = eb2 + (j << 3) + g;
                b[j][0] = TP[(kl + tg) * 72 + ec];
                b[j][1] = TP[(kl + tg + 4) * 72 + ec];
            }
#pragma unroll
            for (int i = 0; i < 2; i++)
#pragma unroll
                for (int j = 0; j < 4; j++)
                    mma8(c[i][j], a[i][0], a[i][1], a[i][2], a[i][3],
                         b[j][0], b[j][1]);
        }
    }

    __syncthreads();
    if (sub == 0) {
#pragma unroll
        for (int i = 0; i < 2; i++) {
            int row = rb2 + (i << 4) + g;
#pragma unroll
            for (int j = 0; j < 4; j++) {
                int col = eb2 + (j << 3) + (tg << 1);
                OB68[row * 68 + col]           = c[i][j][0];
                OB68[row * 68 + col + 1]       = c[i][j][1];
                OB68[(row + 8) * 68 + col]     = c[i][j][2];
                OB68[(row + 8) * 68 + col + 1] = c[i][j][3];
            }
        }
    }
    __syncthreads();
    if (sub == 1) {
#pragma unroll
        for (int i = 0; i < 2; i++) {
            int row = rb2 + (i << 4) + g;
            float d0 = dinv[row], d1 = dinv[row + 8];
#pragma unroll
            for (int j = 0; j < 4; j++) {
                int col = eb2 + (j << 3) + (tg << 1);
                float2 v0, v1;
                v0.x = (c[i][j][0] + OB68[row * 68 + col])           * d0;
                v0.y = (c[i][j][1] + OB68[row * 68 + col + 1])       * d0;
                v1.x = (c[i][j][2] + OB68[(row + 8) * 68 + col])     * d1;
                v1.y = (c[i][j][3] + OB68[(row + 8) * 68 + col + 1]) * d1;
                *(float2*)(Out + ((size_t)bh * NSEQ + n0 + row) * EDIM + col)     = v0;
                *(float2*)(Out + ((size_t)bh * NSEQ + n0 + row + 8) * EDIM + col) = v1;
            }
        }
    }
}

// ------------------------------ launch -------------------------------------
extern "C" void kernel_launch(void* const* d_in, const int* in_sizes, int n_in,
                              void* d_out, int out_size) {
    const float* q = (const float*)d_in[0];
    const float* k = (const float*)d_in[1];
    const float* v = (const float*)d_in[2];
    const float* P = (const float*)d_in[3];
    float* out = (float*)d_out;

    cudaFuncSetAttribute(k1_kdash, cudaFuncAttributeMaxDynamicSharedMemorySize,
                         K1_BYTES);
    cudaFuncSetAttribute(k3_out, cudaFuncAttributeMaxDynamicSharedMemorySize,
                         SM3_BYTES);

    k0_init<<<256, 256>>>();
    k1_kdash<<<dim3(NSEQ / 128, BH), 256, K1_BYTES>>>(k, P);
    k2_context<<<dim3(5, BH, 4), 256>>>(v);
    k3_out<<<dim3(NSEQ / 64, BH), 256, SM3_BYTES>>>(q, P, out);
}